// round 9
// baseline (speedup 1.0000x reference)
#include <cuda_runtime.h>
#include <cstdint>

// Bond-percolation flood fill, 8192x8192 periodic lattice.
//   in[0] links : int32 (2,8192,8192) {0,1}   (512 MB)
//   in[1] seed  : int32 (2,)
//   out         : float32 (8192,8192), cluster cells = 1.0f
// p=0.45 < pc=0.5 -> seed cluster is tiny.
//
// R8 passed at 47.9us = memset(256MB, ~33us) + BFS(10.4us) serialized.
// This round overlaps them in ONE kernel:
//   blocks 1..NB-1 : zero `out` (uint4 streaming stores, DRAM-write bound)
//   block 0        : BFS into a static visited bitmap + queue (latency bound,
//                    touches only a few KB of links -> no bandwidth conflict)
//   handshake      : zero-blocks release-increment g_done; block 0 acquires,
//                    then scatters 1.0f into cluster cells and clears exactly
//                    the visited bits it set (state returns to all-zero ->
//                    deterministic across graph replays).
// g_done is reset per launch by a 4-byte memset node.

#define GRID_N 8192
#define LOG2_N 13
#define NCELLS (GRID_N * GRID_N)
#define QCAP   (1 << 22)          // 16 MB static queue
#define ONE_F  0x3F800000u        // 1.0f bit pattern
#define NB     592                // total blocks (1 BFS + 591 zeroing)
#define NTHR   256

__device__ int          g_done;                  // zero-block completion count
__device__ unsigned int g_visited[NCELLS / 32];  // 8 MB bitmap (zero-init)
__device__ int          d_queue[QCAP];

__global__ void __launch_bounds__(NTHR, 8)
fused_kernel(const unsigned int* __restrict__ links,
             const int* __restrict__ seed,
             unsigned int* __restrict__ out)
{
    const int tid = threadIdx.x;

    // ---------------------------------------------------- zeroing blocks ---
    if (blockIdx.x != 0) {
        const int w  = blockIdx.x - 1;          // worker id 0..NB-2
        const int NW = NB - 1;
        uint4* o = reinterpret_cast<uint4*>(out);
        const unsigned int n16 = NCELLS / 4;    // 16M uint4 = 256 MB
        const uint4 z = make_uint4(0u, 0u, 0u, 0u);
        for (unsigned int i = (unsigned int)w * NTHR + tid; i < n16;
             i += (unsigned int)NW * NTHR)
            o[i] = z;
        __threadfence();                        // publish stores
        __syncthreads();                        // whole block done
        if (tid == 0) atomicAdd(&g_done, 1);    // release
        return;
    }

    // --------------------------------------------------------- BFS block ---
    const unsigned int* __restrict__ L0 = links;            // +axis0 bonds
    const unsigned int* __restrict__ L1 = links + NCELLS;   // +axis1 bonds

    __shared__ int s_start, s_end, s_next, s_ovf;

    if (tid == 0) {
        const int a = seed[0] & (GRID_N - 1);
        const int b = seed[1] & (GRID_N - 1);
        const int idx = (a << LOG2_N) | b;
        atomicOr(&g_visited[idx >> 5], 1u << (idx & 31));
        d_queue[0] = idx;
        s_start = 0; s_end = 1; s_next = 1; s_ovf = 0;
    }
    __syncthreads();

    while (true) {
        const int start = s_start;
        const int end   = s_end;
        if (start >= end) break;

        for (int i = start + tid; i < end; i += NTHR) {
            const int idx = d_queue[i];
            const int a = idx >> LOG2_N;
            const int b = idx & (GRID_N - 1);

            // periodic 4-neighborhood:
            //   bond L0[a,b] connects (a,b)<->(a+1,b)
            //   bond L1[a,b] connects (a,b)<->(a,b+1)
            const int nA = (((a + 1) & (GRID_N - 1)) << LOG2_N) | b;
            const int mA = (((a - 1) & (GRID_N - 1)) << LOG2_N) | b;
            const int nB = (a << LOG2_N) | ((b + 1) & (GRID_N - 1));
            const int mB = (a << LOG2_N) | ((b - 1) & (GRID_N - 1));

            const bool o0 = L0[idx] != 0u;
            const bool o1 = L0[mA]  != 0u;
            const bool o2 = L1[idx] != 0u;
            const bool o3 = L1[mB]  != 0u;

            const int  nbr[4] = { nA, mA, nB, mB };
            const bool op [4] = { o0, o1, o2, o3 };

            #pragma unroll
            for (int d = 0; d < 4; d++) {
                if (!op[d]) continue;
                const int m = nbr[d];
                const unsigned int bit = 1u << (m & 31);
                if ((atomicOr(&g_visited[m >> 5], bit) & bit) == 0u) {
                    const int p = atomicAdd(&s_next, 1);
                    if (p < QCAP) d_queue[p] = m;
                    else          s_ovf = 1;          // clamp (never expected)
                }
            }
        }
        __syncthreads();
        if (tid == 0) {
            s_start = s_end;
            s_end   = (s_next < QCAP) ? s_next : QCAP;
        }
        __syncthreads();
    }

    const int count = (s_next < QCAP) ? s_next : QCAP;
    const int ovf   = s_ovf;

    // ------------------------------------------- wait for zeroing blocks ---
    if (tid == 0)
        while (atomicAdd(&g_done, 0) < NB - 1) { }
    __syncthreads();
    __threadfence();                             // acquire zero-block stores

    // ------------------------------------------- scatter 1.0f + cleanup ----
    for (int i = tid; i < count; i += NTHR)
        out[d_queue[i]] = ONE_F;

    if (!ovf) {
        // clear exactly the bits we set -> bitmap returns to all-zero
        for (int i = tid; i < count; i += NTHR) {
            const int m = d_queue[i];
            atomicAnd(&g_visited[m >> 5], ~(1u << (m & 31)));
        }
    } else {
        // safety path (unreachable for subcritical clusters): full clear
        for (unsigned int i = tid; i < NCELLS / 32; i += NTHR)
            g_visited[i] = 0u;
    }
}

extern "C" void kernel_launch(void* const* d_in, const int* in_sizes, int n_in,
                              void* d_out, int out_size)
{
    const unsigned int* links = (const unsigned int*)d_in[0];
    const int*          seed  = (const int*)d_in[1];
    unsigned int*       out   = (unsigned int*)d_out;
    (void)in_sizes; (void)n_in; (void)out_size;

    // Reset the handshake counter (4-byte memset node, ~0 cost).
    void* done_addr = nullptr;
    cudaGetSymbolAddress(&done_addr, g_done);
    cudaMemsetAsync(done_addr, 0, sizeof(int));

    fused_kernel<<<NB, NTHR>>>(links, seed, out);
}